// round 5
// baseline (speedup 1.0000x reference)
#include <cuda_runtime.h>
#include <cuda_bf16.h>
#include <math.h>

// Problem constants
#define BB 8
#define MM 256
#define EE 128
#define KK 16
#define HH 1024
#define AA 256
#define RR 1024
#define RMS 512
#define BE (BB*EE)          // 1024
#define BM_TOT (BB*MM)      // 2048 unique mentions
#define ZW (HH + RMS)       // 1536

// Scratch (device globals; allocation is forbidden)
__device__ float g_P[BM_TOT * 2 * AA];  // [2048, 512]: cols 0..255 = Pv, 256..511 = Pu
__device__ float g_L[BM_TOT];           // per-mention logits
__device__ float g_attn[BE * KK];
__device__ float g_E[BE * HH];          // entity reprs
__device__ float g_swT[HH * RR];        // (RM @ Wr^T + br)^T  [1024,1024]
__device__ float g_RMt[RMS * RR];       // RM^T [512,1024]
__device__ float g_T[HH * RMS];         // swT @ RM  [1024,512]
__device__ float g_G[HH * HH];          // Wo1 + Wo2 @ T^T (transposed eff. weight)

// ---------------------------------------------------------------------------
// Packed f32x2 helpers (Blackwell FFMA2 — only reachable via PTX)
// ---------------------------------------------------------------------------
#define FMA_X2(d, a, b) \
    asm("fma.rn.f32x2 %0, %1, %2, %0;" : "+l"(d) : "l"(a), "l"(b))
#define PACK_DUP(out, f) \
    asm("mov.b64 %0, {%1, %1};" : "=l"(out) : "f"(f))
#define UNPACK_X2(lo, hi, in) \
    asm("mov.b64 {%0, %1}, %2;" : "=f"(lo), "=f"(hi) : "l"(in))

// ---------------------------------------------------------------------------
// Double-buffered fp32 NT GEMM using fma.rn.f32x2:
//   C[M,N] = A[M,K] * B[N,K]^T (+ epilogue)
// BM=BN=128, BK=16, 256 threads, 8x8 per-thread tile (acc paired along M).
// MODE: 0=none, 1=col bias (bias[n]), 2=add Cadd matrix, 3=row bias (bias[m])
// ---------------------------------------------------------------------------
#define BM 128
#define BN 128
#define BK 16

template<int MODE>
__global__ void __launch_bounds__(256)
sgemm_nt(const float* __restrict__ A, const float* __restrict__ B,
         const float* __restrict__ bias, const float* __restrict__ Cadd,
         float* __restrict__ C, int lda, int ldb, int ldc, int ldadd, int Kdim)
{
    __shared__ float As[2][BK][BM + 4];
    __shared__ float Bs[2][BK][BN + 4];

    const int tid = threadIdx.x;
    const int bx = blockIdx.x;   // N tiles
    const int by = blockIdx.y;   // M tiles

    const int r0 = tid >> 2;           // 0..63
    const int c4 = (tid & 3) << 2;     // 0,4,8,12

    const float* aptr0 = A + (size_t)(by * BM + r0)      * lda + c4;
    const float* aptr1 = A + (size_t)(by * BM + r0 + 64) * lda + c4;
    const float* bptr0 = B + (size_t)(bx * BN + r0)      * ldb + c4;
    const float* bptr1 = B + (size_t)(bx * BN + r0 + 64) * ldb + c4;

    const int tx = tid & 15;   // N dir -> cols tx*8..tx*8+7
    const int ty = tid >> 4;   // M dir -> rows ty*8..ty*8+7

    unsigned long long acc[4][8];
#pragma unroll
    for (int i = 0; i < 4; i++)
#pragma unroll
        for (int j = 0; j < 8; j++) acc[i][j] = 0ull;

    float4 ra0, ra1, rb0, rb1;

    // prologue: tile 0 -> buf 0
    ra0 = *(const float4*)aptr0;
    ra1 = *(const float4*)aptr1;
    rb0 = *(const float4*)bptr0;
    rb1 = *(const float4*)bptr1;
#pragma unroll
    for (int q = 0; q < 4; q++) {
        As[0][c4 + q][r0]      = ((const float*)&ra0)[q];
        As[0][c4 + q][r0 + 64] = ((const float*)&ra1)[q];
        Bs[0][c4 + q][r0]      = ((const float*)&rb0)[q];
        Bs[0][c4 + q][r0 + 64] = ((const float*)&rb1)[q];
    }
    __syncthreads();

    const int nK = Kdim >> 4;
    int buf = 0;
    for (int t = 0; t < nK; t++) {
        const bool more = (t + 1 < nK);
        if (more) {
            const int k0 = (t + 1) * BK;
            ra0 = *(const float4*)(aptr0 + k0);
            ra1 = *(const float4*)(aptr1 + k0);
            rb0 = *(const float4*)(bptr0 + k0);
            rb1 = *(const float4*)(bptr1 + k0);
        }
#pragma unroll
        for (int kk = 0; kk < BK; kk++) {
            // A pairs along M: 4 packed pairs via two 16B loads
            const float* as = &As[buf][kk][ty * 8];
            ulonglong2 am01 = *(const ulonglong2*)(as);
            ulonglong2 am23 = *(const ulonglong2*)(as + 4);
            unsigned long long am[4] = {am01.x, am01.y, am23.x, am23.y};
            // B: 8 scalars, broadcast-packed
            float4 bf0 = *(const float4*)&Bs[buf][kk][tx * 8];
            float4 bf1 = *(const float4*)&Bs[buf][kk][tx * 8 + 4];
            unsigned long long bb[8];
            PACK_DUP(bb[0], bf0.x); PACK_DUP(bb[1], bf0.y);
            PACK_DUP(bb[2], bf0.z); PACK_DUP(bb[3], bf0.w);
            PACK_DUP(bb[4], bf1.x); PACK_DUP(bb[5], bf1.y);
            PACK_DUP(bb[6], bf1.z); PACK_DUP(bb[7], bf1.w);
#pragma unroll
            for (int i = 0; i < 4; i++)
#pragma unroll
                for (int j = 0; j < 8; j++)
                    FMA_X2(acc[i][j], am[i], bb[j]);
        }
        if (more) {
            const int nb = buf ^ 1;
#pragma unroll
            for (int q = 0; q < 4; q++) {
                As[nb][c4 + q][r0]      = ((const float*)&ra0)[q];
                As[nb][c4 + q][r0 + 64] = ((const float*)&ra1)[q];
                Bs[nb][c4 + q][r0]      = ((const float*)&rb0)[q];
                Bs[nb][c4 + q][r0 + 64] = ((const float*)&rb1)[q];
            }
        }
        __syncthreads();
        buf ^= 1;
    }

    // epilogue
    const int cm = by * BM + ty * 8;
    const int cn = bx * BN + tx * 8;
    float4 bc0 = make_float4(0.f, 0.f, 0.f, 0.f);
    float4 bc1 = make_float4(0.f, 0.f, 0.f, 0.f);
    if (MODE == 1) {
        bc0 = *(const float4*)(bias + cn);
        bc1 = *(const float4*)(bias + cn + 4);
    }
#pragma unroll
    for (int i = 0; i < 4; i++) {
        float lo[8], hi[8];
#pragma unroll
        for (int j = 0; j < 8; j++) UNPACK_X2(lo[j], hi[j], acc[i][j]);
        const int rA = cm + 2 * i;
        const int rB = rA + 1;
        float4 vA0 = make_float4(lo[0], lo[1], lo[2], lo[3]);
        float4 vA1 = make_float4(lo[4], lo[5], lo[6], lo[7]);
        float4 vB0 = make_float4(hi[0], hi[1], hi[2], hi[3]);
        float4 vB1 = make_float4(hi[4], hi[5], hi[6], hi[7]);
        if (MODE == 1) {
            vA0.x += bc0.x; vA0.y += bc0.y; vA0.z += bc0.z; vA0.w += bc0.w;
            vA1.x += bc1.x; vA1.y += bc1.y; vA1.z += bc1.z; vA1.w += bc1.w;
            vB0.x += bc0.x; vB0.y += bc0.y; vB0.z += bc0.z; vB0.w += bc0.w;
            vB1.x += bc1.x; vB1.y += bc1.y; vB1.z += bc1.z; vB1.w += bc1.w;
        }
        if (MODE == 3) {
            float ra = bias[rA], rb = bias[rB];
            vA0.x += ra; vA0.y += ra; vA0.z += ra; vA0.w += ra;
            vA1.x += ra; vA1.y += ra; vA1.z += ra; vA1.w += ra;
            vB0.x += rb; vB0.y += rb; vB0.z += rb; vB0.w += rb;
            vB1.x += rb; vB1.y += rb; vB1.z += rb; vB1.w += rb;
        }
        if (MODE == 2) {
            float4 cA0 = *(const float4*)(Cadd + (size_t)rA * ldadd + cn);
            float4 cA1 = *(const float4*)(Cadd + (size_t)rA * ldadd + cn + 4);
            float4 cB0 = *(const float4*)(Cadd + (size_t)rB * ldadd + cn);
            float4 cB1 = *(const float4*)(Cadd + (size_t)rB * ldadd + cn + 4);
            vA0.x += cA0.x; vA0.y += cA0.y; vA0.z += cA0.z; vA0.w += cA0.w;
            vA1.x += cA1.x; vA1.y += cA1.y; vA1.z += cA1.z; vA1.w += cA1.w;
            vB0.x += cB0.x; vB0.y += cB0.y; vB0.z += cB0.z; vB0.w += cB0.w;
            vB1.x += cB1.x; vB1.y += cB1.y; vB1.z += cB1.z; vB1.w += cB1.w;
        }
        *(float4*)&C[(size_t)rA * ldc + cn]     = vA0;
        *(float4*)&C[(size_t)rA * ldc + cn + 4] = vA1;
        *(float4*)&C[(size_t)rB * ldc + cn]     = vB0;
        *(float4*)&C[(size_t)rB * ldc + cn + 4] = vB1;
    }
}

// ---------------------------------------------------------------------------
// Per-mention MIL logit: L[row] = Wa . (tanh(Pv+bv) * sigmoid(Pu+bu)) + ba
// One warp per mention row (2048 rows).
// ---------------------------------------------------------------------------
__global__ void __launch_bounds__(256)
mil_logits(const float* __restrict__ P, const float* __restrict__ bv,
           const float* __restrict__ bu, const float* __restrict__ Wa,
           const float* __restrict__ ba, float* __restrict__ L)
{
    const int w = (blockIdx.x * 256 + threadIdx.x) >> 5;   // 0..2047
    const int lane = threadIdx.x & 31;
    const float* p = P + (size_t)w * (2 * AA);
    float sum = 0.f;
#pragma unroll
    for (int j = 0; j < 8; j++) {
        int a = lane + j * 32;
        float v = tanhf(p[a] + bv[a]);
        float u = 1.f / (1.f + expf(-(p[AA + a] + bu[a])));
        sum += v * u * Wa[a];
    }
#pragma unroll
    for (int o = 16; o; o >>= 1) sum += __shfl_xor_sync(0xffffffffu, sum, o);
    if (lane == 0) L[w] = sum + ba[0];
}

// ---------------------------------------------------------------------------
// Gather per-mention logits, mask, softmax over K=16. One warp per (b,e).
// ---------------------------------------------------------------------------
__global__ void __launch_bounds__(256)
softmax16(const float* __restrict__ L, const int* __restrict__ ent,
          const int* __restrict__ mask, float* __restrict__ attn)
{
    const int w = (blockIdx.x * 256 + threadIdx.x) >> 5;   // be: 0..1023
    const int lane = threadIdx.x & 31;
    const int idx = w * KK + (lane & 15);
    float l = -1e30f;
    if (lane < KK) {
        int m = ent[idx];
        l = mask[idx] ? L[(w >> 7) * MM + m] : -1e25f;
    }
    float mx = l;
#pragma unroll
    for (int o = 8; o; o >>= 1) mx = fmaxf(mx, __shfl_xor_sync(0xffffffffu, mx, o));
    float e = expf(l - mx);
    float s = e;
#pragma unroll
    for (int o = 8; o; o >>= 1) s += __shfl_xor_sync(0xffffffffu, s, o);
    if (lane < KK) attn[idx] = e / s;
}

// ---------------------------------------------------------------------------
// Weighted pooling over K mentions -> entity reprs g_E [BE, H]
// ---------------------------------------------------------------------------
__global__ void __launch_bounds__(256)
pool_kernel(const float* __restrict__ attn, const int* __restrict__ ent,
            const float* __restrict__ mr, float* __restrict__ E)
{
    const int be = blockIdx.x;
    const int b = be >> 7;   // /E
    __shared__ float w[KK];
    __shared__ int rows[KK];
    if (threadIdx.x < KK) {
        w[threadIdx.x] = attn[be * KK + threadIdx.x];
        rows[threadIdx.x] = b * MM + ent[be * KK + threadIdx.x];
    }
    __syncthreads();
    for (int h = threadIdx.x; h < HH; h += 256) {
        float s = 0.f;
#pragma unroll
        for (int k = 0; k < KK; k++)
            s = fmaf(w[k], mr[(size_t)rows[k] * HH + h], s);
        E[(size_t)be * HH + h] = s;
    }
}

// ---------------------------------------------------------------------------
// Transpose relation_memory [R, RMS] -> RMt [RMS, R]
// ---------------------------------------------------------------------------
__global__ void __launch_bounds__(1024)
transpose_rm(const float* __restrict__ RM, float* __restrict__ RMt)
{
    __shared__ float t[32][33];
    const int r0 = blockIdx.y * 32;
    const int m0 = blockIdx.x * 32;
    t[threadIdx.y][threadIdx.x] = RM[(size_t)(r0 + threadIdx.y) * RMS + m0 + threadIdx.x];
    __syncthreads();
    RMt[(size_t)(m0 + threadIdx.y) * RR + r0 + threadIdx.x] = t[threadIdx.x][threadIdx.y];
}

// ---------------------------------------------------------------------------
extern "C" void kernel_launch(void* const* d_in, const int* in_sizes, int n_in,
                              void* d_out, int out_size)
{
    const float* mr   = (const float*)d_in[0];
    const int*   ent  = (const int*)  d_in[1];
    const int*   emask= (const int*)  d_in[2];
    const float* RM   = (const float*)d_in[3];
    const float* Wv   = (const float*)d_in[4];
    const float* bv   = (const float*)d_in[5];
    const float* Wu   = (const float*)d_in[6];
    const float* bu   = (const float*)d_in[7];
    const float* Wa   = (const float*)d_in[8];
    const float* ba   = (const float*)d_in[9];
    const float* Wr   = (const float*)d_in[10];
    const float* br   = (const float*)d_in[11];
    const float* Wo   = (const float*)d_in[12];
    const float* bo   = (const float*)d_in[13];
    float* out = (float*)d_out;

    float *P, *L, *attn, *E, *swT, *RMt, *T, *G;
    cudaGetSymbolAddress((void**)&P,   g_P);
    cudaGetSymbolAddress((void**)&L,   g_L);
    cudaGetSymbolAddress((void**)&attn,g_attn);
    cudaGetSymbolAddress((void**)&E,   g_E);
    cudaGetSymbolAddress((void**)&swT, g_swT);
    cudaGetSymbolAddress((void**)&RMt, g_RMt);
    cudaGetSymbolAddress((void**)&T,   g_T);
    cudaGetSymbolAddress((void**)&G,   g_G);

    // Side streams/events for graph-level parallelism (created once; host-side
    // resources only, no device memory).
    static cudaStream_t s1 = nullptr, s2 = nullptr, s3 = nullptr;
    static cudaEvent_t eR = nullptr, e1 = nullptr, e2 = nullptr, e3 = nullptr;
    if (!s1) {
        cudaStreamCreateWithFlags(&s1, cudaStreamNonBlocking);
        cudaStreamCreateWithFlags(&s2, cudaStreamNonBlocking);
        cudaStreamCreateWithFlags(&s3, cudaStreamNonBlocking);
        cudaEventCreateWithFlags(&eR, cudaEventDisableTiming);
        cudaEventCreateWithFlags(&e1, cudaEventDisableTiming);
        cudaEventCreateWithFlags(&e2, cudaEventDisableTiming);
        cudaEventCreateWithFlags(&e3, cudaEventDisableTiming);
    }

    // fork
    cudaEventRecord(eR, 0);
    cudaStreamWaitEvent(s1, eR, 0);
    cudaStreamWaitEvent(s2, eR, 0);
    cudaStreamWaitEvent(s3, eR, 0);

    // --- branch A1 (s1): Pv = MR @ Wv^T  -> P[:, 0:256]  (N = AA = 256) ---
    sgemm_nt<0><<<dim3(AA / BN, BM_TOT / BM), 256, 0, s1>>>(
        mr, Wv, nullptr, nullptr, P, HH, HH, 2 * AA, 0, HH);
    cudaEventRecord(e1, s1);

    // --- branch A2 (s2): Pu = MR @ Wu^T  -> P[:, 256:512]  (N = AA = 256) ---
    sgemm_nt<0><<<dim3(AA / BN, BM_TOT / BM), 256, 0, s2>>>(
        mr, Wu, nullptr, nullptr, P + AA, HH, HH, 2 * AA, 0, HH);
    cudaEventRecord(e2, s2);

    // --- branch B (s3): effective output weight G ---
    transpose_rm<<<dim3(RMS / 32, RR / 32), dim3(32, 32), 0, s3>>>(RM, RMt);
    // swT[h,r] = Wr[h,:] . RM[r,:] + br[h]
    sgemm_nt<3><<<dim3(RR / BN, HH / BM), 256, 0, s3>>>(
        Wr, RM, br, nullptr, swT, RMS, RMS, RR, 0, RMS);
    // T[h,m] = swT[h,:] . RMt[m,:]
    sgemm_nt<0><<<dim3(RMS / BN, HH / BM), 256, 0, s3>>>(
        swT, RMt, nullptr, nullptr, T, RR, RR, RMS, 0, RR);
    // G[h',h] = Wo2[h',:] . T[h,:] + Wo1[h',h]
    sgemm_nt<2><<<dim3(HH / BN, HH / BM), 256, 0, s3>>>(
        Wo + HH, T, nullptr, Wo, G, ZW, RMS, HH, ZW, RMS);
    cudaEventRecord(e3, s3);

    // --- default stream: attention chain after Pv,Pu ---
    cudaStreamWaitEvent(0, e1, 0);
    cudaStreamWaitEvent(0, e2, 0);
    mil_logits<<<BM_TOT / 8, 256>>>(P, bv, bu, Wa, ba, L);
    softmax16<<<BE / 8, 256>>>(L, ent, emask, attn);
    pool_kernel<<<BE, 256>>>(attn, ent, mr, E);

    // join with branch B, then final GEMM
    cudaStreamWaitEvent(0, e3, 0);
    // out[i,h'] = E[i,:] . G[h',:] + bo[h']
    sgemm_nt<1><<<dim3(HH / BN, BE / BM), 256>>>(
        E, G, bo, nullptr, out, HH, HH, HH, 0, HH);

    (void)in_sizes; (void)n_in; (void)out_size;
}

// round 6
// speedup vs baseline: 1.6301x; 1.6301x over previous
#include <cuda_runtime.h>
#include <cuda_bf16.h>
#include <math.h>

// Problem constants
#define BB 8
#define MM 256
#define EE 128
#define KK 16
#define HH 1024
#define AA 256
#define RR 1024
#define RMS 512
#define BE (BB*EE)          // 1024
#define BM_TOT (BB*MM)      // 2048 unique mentions
#define ZW (HH + RMS)       // 1536

// Scratch (device globals; allocation is forbidden)
__device__ float g_P[BM_TOT * 2 * AA];  // [2048, 512]: cols 0..255 = Pv, 256..511 = Pu
__device__ float g_L[BM_TOT];           // per-mention logits
__device__ float g_attn[BE * KK];
__device__ float g_E[BE * HH];          // entity reprs
__device__ float g_RMt[RMS * RR];       // RM^T [512,1024]
__device__ float g_C[RMS * RMS];        // RM^T RM (Gram, symmetric) [512,512]
__device__ float g_r[RMS];              // colsum(RM) [512]
__device__ float g_Teff[HH * RMS];      // Wr·C + br·r^T  [1024,512]
__device__ float g_G[HH * HH];          // Wo1 + Wo2·Teff^T [1024,1024]

// ---------------------------------------------------------------------------
// Packed f32x2 helpers (Blackwell FFMA2 — only reachable via PTX)
// ---------------------------------------------------------------------------
#define FMA_X2(d, a, b) \
    asm("fma.rn.f32x2 %0, %1, %2, %0;" : "+l"(d) : "l"(a), "l"(b))
#define PACK_DUP(out, f) \
    asm("mov.b64 %0, {%1, %1};" : "=l"(out) : "f"(f))
#define UNPACK_X2(lo, hi, in) \
    asm("mov.b64 {%0, %1}, %2;" : "=f"(lo), "=f"(hi) : "l"(in))

// ---------------------------------------------------------------------------
// Double-buffered fp32 NT GEMM using fma.rn.f32x2:
//   C[M,N] = A[M,K] * B[N,K]^T (+ epilogue)
// BM=BN=64, BK=16, 128 threads, 8x4 per-thread tile (acc paired along M).
// MODE: 0=none, 1=col bias (bias[n]), 2=add Cadd matrix,
//       4=outer product bias[m]*bias2[n]
// ---------------------------------------------------------------------------
#define BM 64
#define BN 64
#define BK 16

template<int MODE>
__global__ void __launch_bounds__(128)
sgemm_nt(const float* __restrict__ A, const float* __restrict__ B,
         const float* __restrict__ bias, const float* __restrict__ bias2,
         const float* __restrict__ Cadd,
         float* __restrict__ C, int lda, int ldb, int ldc, int ldadd, int Kdim)
{
    __shared__ float As[2][BK][BM + 4];
    __shared__ float Bs[2][BK][BN + 4];

    const int tid = threadIdx.x;
    const int bx = blockIdx.x;   // N tiles
    const int by = blockIdx.y;   // M tiles

    const int r0 = tid >> 2;           // 0..31
    const int c4 = (tid & 3) << 2;     // 0,4,8,12

    const float* aptr0 = A + (size_t)(by * BM + r0)      * lda + c4;
    const float* aptr1 = A + (size_t)(by * BM + r0 + 32) * lda + c4;
    const float* bptr0 = B + (size_t)(bx * BN + r0)      * ldb + c4;
    const float* bptr1 = B + (size_t)(bx * BN + r0 + 32) * ldb + c4;

    const int tx = tid & 15;   // N dir -> cols tx*4..tx*4+3
    const int ty = tid >> 4;   // M dir -> rows ty*8..ty*8+7 (4 pairs)

    unsigned long long acc[4][4];
#pragma unroll
    for (int i = 0; i < 4; i++)
#pragma unroll
        for (int j = 0; j < 4; j++) acc[i][j] = 0ull;

    float4 ra0, ra1, rb0, rb1;

    // prologue: tile 0 -> buf 0
    ra0 = *(const float4*)aptr0;
    ra1 = *(const float4*)aptr1;
    rb0 = *(const float4*)bptr0;
    rb1 = *(const float4*)bptr1;
#pragma unroll
    for (int q = 0; q < 4; q++) {
        As[0][c4 + q][r0]      = ((const float*)&ra0)[q];
        As[0][c4 + q][r0 + 32] = ((const float*)&ra1)[q];
        Bs[0][c4 + q][r0]      = ((const float*)&rb0)[q];
        Bs[0][c4 + q][r0 + 32] = ((const float*)&rb1)[q];
    }
    __syncthreads();

    const int nK = Kdim >> 4;
    int buf = 0;
    for (int t = 0; t < nK; t++) {
        const bool more = (t + 1 < nK);
        if (more) {
            const int k0 = (t + 1) * BK;
            ra0 = *(const float4*)(aptr0 + k0);
            ra1 = *(const float4*)(aptr1 + k0);
            rb0 = *(const float4*)(bptr0 + k0);
            rb1 = *(const float4*)(bptr1 + k0);
        }
#pragma unroll
        for (int kk = 0; kk < BK; kk++) {
            // A pairs along M: 4 packed pairs via two 16B loads
            const float* as = &As[buf][kk][ty * 8];
            ulonglong2 am01 = *(const ulonglong2*)(as);
            ulonglong2 am23 = *(const ulonglong2*)(as + 4);
            unsigned long long am[4] = {am01.x, am01.y, am23.x, am23.y};
            // B: 4 scalars, broadcast-packed
            float4 bf = *(const float4*)&Bs[buf][kk][tx * 4];
            unsigned long long bb[4];
            PACK_DUP(bb[0], bf.x); PACK_DUP(bb[1], bf.y);
            PACK_DUP(bb[2], bf.z); PACK_DUP(bb[3], bf.w);
#pragma unroll
            for (int i = 0; i < 4; i++)
#pragma unroll
                for (int j = 0; j < 4; j++)
                    FMA_X2(acc[i][j], am[i], bb[j]);
        }
        if (more) {
            const int nb = buf ^ 1;
#pragma unroll
            for (int q = 0; q < 4; q++) {
                As[nb][c4 + q][r0]      = ((const float*)&ra0)[q];
                As[nb][c4 + q][r0 + 32] = ((const float*)&ra1)[q];
                Bs[nb][c4 + q][r0]      = ((const float*)&rb0)[q];
                Bs[nb][c4 + q][r0 + 32] = ((const float*)&rb1)[q];
            }
        }
        __syncthreads();
        buf ^= 1;
    }

    // epilogue
    const int cm = by * BM + ty * 8;
    const int cn = bx * BN + tx * 4;
    float4 bc = make_float4(0.f, 0.f, 0.f, 0.f);
    if (MODE == 1) bc = *(const float4*)(bias + cn);
    float4 b2 = make_float4(0.f, 0.f, 0.f, 0.f);
    if (MODE == 4) b2 = *(const float4*)(bias2 + cn);
#pragma unroll
    for (int i = 0; i < 4; i++) {
        float lo[4], hi[4];
#pragma unroll
        for (int j = 0; j < 4; j++) UNPACK_X2(lo[j], hi[j], acc[i][j]);
        const int rA = cm + 2 * i;
        const int rB = rA + 1;
        float4 vA = make_float4(lo[0], lo[1], lo[2], lo[3]);
        float4 vB = make_float4(hi[0], hi[1], hi[2], hi[3]);
        if (MODE == 1) {
            vA.x += bc.x; vA.y += bc.y; vA.z += bc.z; vA.w += bc.w;
            vB.x += bc.x; vB.y += bc.y; vB.z += bc.z; vB.w += bc.w;
        }
        if (MODE == 4) {
            float ba_ = bias[rA], bb_ = bias[rB];
            vA.x += ba_ * b2.x; vA.y += ba_ * b2.y; vA.z += ba_ * b2.z; vA.w += ba_ * b2.w;
            vB.x += bb_ * b2.x; vB.y += bb_ * b2.y; vB.z += bb_ * b2.z; vB.w += bb_ * b2.w;
        }
        if (MODE == 2) {
            float4 cA = *(const float4*)(Cadd + (size_t)rA * ldadd + cn);
            float4 cB = *(const float4*)(Cadd + (size_t)rB * ldadd + cn);
            vA.x += cA.x; vA.y += cA.y; vA.z += cA.z; vA.w += cA.w;
            vB.x += cB.x; vB.y += cB.y; vB.z += cB.z; vB.w += cB.w;
        }
        *(float4*)&C[(size_t)rA * ldc + cn] = vA;
        *(float4*)&C[(size_t)rB * ldc + cn] = vB;
    }
}

// ---------------------------------------------------------------------------
// Per-mention MIL logit: L[row] = Wa . (tanh(Pv+bv) * sigmoid(Pu+bu)) + ba
// One warp per mention row (2048 rows).
// ---------------------------------------------------------------------------
__global__ void __launch_bounds__(256)
mil_logits(const float* __restrict__ P, const float* __restrict__ bv,
           const float* __restrict__ bu, const float* __restrict__ Wa,
           const float* __restrict__ ba, float* __restrict__ L)
{
    const int w = (blockIdx.x * 256 + threadIdx.x) >> 5;   // 0..2047
    const int lane = threadIdx.x & 31;
    const float* p = P + (size_t)w * (2 * AA);
    float sum = 0.f;
#pragma unroll
    for (int j = 0; j < 8; j++) {
        int a = lane + j * 32;
        float v = tanhf(p[a] + bv[a]);
        float u = 1.f / (1.f + expf(-(p[AA + a] + bu[a])));
        sum += v * u * Wa[a];
    }
#pragma unroll
    for (int o = 16; o; o >>= 1) sum += __shfl_xor_sync(0xffffffffu, sum, o);
    if (lane == 0) L[w] = sum + ba[0];
}

// ---------------------------------------------------------------------------
// Gather per-mention logits, mask, softmax over K=16. One warp per (b,e).
// ---------------------------------------------------------------------------
__global__ void __launch_bounds__(256)
softmax16(const float* __restrict__ L, const int* __restrict__ ent,
          const int* __restrict__ mask, float* __restrict__ attn)
{
    const int w = (blockIdx.x * 256 + threadIdx.x) >> 5;   // be: 0..1023
    const int lane = threadIdx.x & 31;
    const int idx = w * KK + (lane & 15);
    float l = -1e30f;
    if (lane < KK) {
        int m = ent[idx];
        l = mask[idx] ? L[(w >> 7) * MM + m] : -1e25f;
    }
    float mx = l;
#pragma unroll
    for (int o = 8; o; o >>= 1) mx = fmaxf(mx, __shfl_xor_sync(0xffffffffu, mx, o));
    float e = expf(l - mx);
    float s = e;
#pragma unroll
    for (int o = 8; o; o >>= 1) s += __shfl_xor_sync(0xffffffffu, s, o);
    if (lane < KK) attn[idx] = e / s;
}

// ---------------------------------------------------------------------------
// Weighted pooling over K mentions -> entity reprs g_E [BE, H]
// ---------------------------------------------------------------------------
__global__ void __launch_bounds__(256)
pool_kernel(const float* __restrict__ attn, const int* __restrict__ ent,
            const float* __restrict__ mr, float* __restrict__ E)
{
    const int be = blockIdx.x;
    const int b = be >> 7;   // /E
    __shared__ float w[KK];
    __shared__ int rows[KK];
    if (threadIdx.x < KK) {
        w[threadIdx.x] = attn[be * KK + threadIdx.x];
        rows[threadIdx.x] = b * MM + ent[be * KK + threadIdx.x];
    }
    __syncthreads();
    for (int h = threadIdx.x; h < HH; h += 256) {
        float s = 0.f;
#pragma unroll
        for (int k = 0; k < KK; k++)
            s = fmaf(w[k], mr[(size_t)rows[k] * HH + h], s);
        E[(size_t)be * HH + h] = s;
    }
}

// ---------------------------------------------------------------------------
// Transpose relation_memory [R, RMS] -> RMt [RMS, R]
// ---------------------------------------------------------------------------
__global__ void __launch_bounds__(1024)
transpose_rm(const float* __restrict__ RM, float* __restrict__ RMt)
{
    __shared__ float t[32][33];
    const int r0 = blockIdx.y * 32;
    const int m0 = blockIdx.x * 32;
    t[threadIdx.y][threadIdx.x] = RM[(size_t)(r0 + threadIdx.y) * RMS + m0 + threadIdx.x];
    __syncthreads();
    RMt[(size_t)(m0 + threadIdx.y) * RR + r0 + threadIdx.x] = t[threadIdx.x][threadIdx.y];
}

// ---------------------------------------------------------------------------
// Column sums of RM: r[m] = sum_r RM[r, m]   (coalesced across m)
// ---------------------------------------------------------------------------
__global__ void __launch_bounds__(128)
colsum_rm(const float* __restrict__ RM, float* __restrict__ r)
{
    const int m = blockIdx.x * 128 + threadIdx.x;   // 512 total
    float s = 0.f;
    for (int i = 0; i < RR; i++) s += RM[(size_t)i * RMS + m];
    r[m] = s;
}

// ---------------------------------------------------------------------------
extern "C" void kernel_launch(void* const* d_in, const int* in_sizes, int n_in,
                              void* d_out, int out_size)
{
    const float* mr   = (const float*)d_in[0];
    const int*   ent  = (const int*)  d_in[1];
    const int*   emask= (const int*)  d_in[2];
    const float* RM   = (const float*)d_in[3];
    const float* Wv   = (const float*)d_in[4];
    const float* bv   = (const float*)d_in[5];
    const float* Wu   = (const float*)d_in[6];
    const float* bu   = (const float*)d_in[7];
    const float* Wa   = (const float*)d_in[8];
    const float* ba   = (const float*)d_in[9];
    const float* Wr   = (const float*)d_in[10];
    const float* br   = (const float*)d_in[11];
    const float* Wo   = (const float*)d_in[12];
    const float* bo   = (const float*)d_in[13];
    float* out = (float*)d_out;

    float *P, *L, *attn, *E, *RMt, *Cg, *rv, *Teff, *G;
    cudaGetSymbolAddress((void**)&P,   g_P);
    cudaGetSymbolAddress((void**)&L,   g_L);
    cudaGetSymbolAddress((void**)&attn,g_attn);
    cudaGetSymbolAddress((void**)&E,   g_E);
    cudaGetSymbolAddress((void**)&RMt, g_RMt);
    cudaGetSymbolAddress((void**)&Cg,  g_C);
    cudaGetSymbolAddress((void**)&rv,  g_r);
    cudaGetSymbolAddress((void**)&Teff,g_Teff);
    cudaGetSymbolAddress((void**)&G,   g_G);

    // Side streams/events (host-side resources only; created once).
    static cudaStream_t s1 = nullptr, s2 = nullptr, s3 = nullptr;
    static cudaEvent_t eR = nullptr, e1 = nullptr, e2 = nullptr, e3 = nullptr;
    if (!s1) {
        cudaStreamCreateWithFlags(&s1, cudaStreamNonBlocking);
        cudaStreamCreateWithFlags(&s2, cudaStreamNonBlocking);
        cudaStreamCreateWithFlags(&s3, cudaStreamNonBlocking);
        cudaEventCreateWithFlags(&eR, cudaEventDisableTiming);
        cudaEventCreateWithFlags(&e1, cudaEventDisableTiming);
        cudaEventCreateWithFlags(&e2, cudaEventDisableTiming);
        cudaEventCreateWithFlags(&e3, cudaEventDisableTiming);
    }

    // fork
    cudaEventRecord(eR, 0);
    cudaStreamWaitEvent(s1, eR, 0);
    cudaStreamWaitEvent(s2, eR, 0);
    cudaStreamWaitEvent(s3, eR, 0);

    // --- branch A1 (s1): Pv = MR @ Wv^T -> P[:,0:256]  grid (4,32)=128 ---
    sgemm_nt<0><<<dim3(AA / BN, BM_TOT / BM), 128, 0, s1>>>(
        mr, Wv, nullptr, nullptr, nullptr, P, HH, HH, 2 * AA, 0, HH);
    cudaEventRecord(e1, s1);

    // --- branch A2 (s2): Pu = MR @ Wu^T -> P[:,256:512]  grid (4,32)=128 ---
    sgemm_nt<0><<<dim3(AA / BN, BM_TOT / BM), 128, 0, s2>>>(
        mr, Wu, nullptr, nullptr, nullptr, P + AA, HH, HH, 2 * AA, 0, HH);
    cudaEventRecord(e2, s2);

    // --- branch B (s3): effective output weight G via Gram matrix ---
    colsum_rm<<<RMS / 128, 128, 0, s3>>>(RM, rv);
    transpose_rm<<<dim3(RMS / 32, RR / 32), dim3(32, 32), 0, s3>>>(RM, RMt);
    // C = RMt @ RMt^T  [512,512,K=1024]  grid (8,8)
    sgemm_nt<0><<<dim3(RMS / BN, RMS / BM), 128, 0, s3>>>(
        RMt, RMt, nullptr, nullptr, nullptr, Cg, RR, RR, RMS, 0, RR);
    // Teff = Wr @ C (C symmetric) + br·r^T  [1024,512,K=512]  grid (8,16)
    sgemm_nt<4><<<dim3(RMS / BN, HH / BM), 128, 0, s3>>>(
        Wr, Cg, br, rv, nullptr, Teff, RMS, RMS, RMS, 0, RMS);
    // G = Wo2 @ Teff^T + Wo1  [1024,1024,K=512]  grid (16,16)
    sgemm_nt<2><<<dim3(HH / BN, HH / BM), 128, 0, s3>>>(
        Wo + HH, Teff, nullptr, nullptr, Wo, G, ZW, RMS, HH, ZW, RMS);
    cudaEventRecord(e3, s3);

    // --- default stream: attention chain after Pv,Pu ---
    cudaStreamWaitEvent(0, e1, 0);
    cudaStreamWaitEvent(0, e2, 0);
    mil_logits<<<BM_TOT / 8, 256>>>(P, bv, bu, Wa, ba, L);
    softmax16<<<BE / 8, 256>>>(L, ent, emask, attn);
    pool_kernel<<<BE, 256>>>(attn, ent, mr, E);

    // join with branch B, then final GEMM
    cudaStreamWaitEvent(0, e3, 0);
    // out = E @ G^T + bo  [1024,1024,K=1024]  grid (16,16)
    sgemm_nt<1><<<dim3(HH / BN, BE / BM), 128>>>(
        E, G, bo, nullptr, nullptr, out, HH, HH, HH, 0, HH);

    (void)in_sizes; (void)n_in; (void)out_size;
}